// round 7
// baseline (speedup 1.0000x reference)
#include <cuda_runtime.h>

// Rows / W2-columns that actually matter (derived from the reshape-select in the
// reference; validated by passing R2/R5 kernels):
//   branch3: slot i<64  -> batch row 64*i,      W2 column 1
//   branch4: slot 64+j  -> rows {0,682,1365,2048,2730,3413}, cols {65,69,67,65,69,67}
__constant__ int c_r4[6] = {0, 682, 1365, 2048, 2730, 3413};
__constant__ int c_c4[6] = {65, 69, 67, 65, 69, 67};

#define SEG3_END   409600
#define BIAS_END   409664

// ---------------------------------------------------------------------------
// Grid = 134 blocks, one wave on 148 SMs:
//   blocks 0..127 : branch-3. slot = b>>1, half = b&1. Both halves compute the
//                   full dot redundantly (L2 dedups the loads); each stores 40
//                   of the 80 output tiles -> per-SM STG work halved vs R5.
//   blocks 128..133: branch-4 (6 x 513 floats) + the 64-float zero gap.
// ---------------------------------------------------------------------------
__global__ void __launch_bounds__(512) fused_kernel(const float* __restrict__ inp,
                                                    const float* __restrict__ W1,
                                                    const float* __restrict__ b1,
                                                    const float* __restrict__ W2,
                                                    const float* __restrict__ b2,
                                                    const float* __restrict__ W3a,
                                                    const float* __restrict__ b3a,
                                                    const float* __restrict__ W3b,
                                                    const float* __restrict__ b3b,
                                                    const float* __restrict__ W4a,
                                                    const float* __restrict__ b4a,
                                                    const float* __restrict__ W4b,
                                                    const float* __restrict__ b4b,
                                                    float* __restrict__ out) {
    __shared__ float warp_sums[16];
    __shared__ float sh_v[80];   // branch3: relu(a*W3b[k]+b3b[k]) per k
    __shared__ float sh_a;       // per-block hidden scalar

    int b    = blockIdx.x;
    int tid  = threadIdx.x;
    int lane = tid & 31;
    int wid  = tid >> 5;

    bool is3 = (b < 128);
    int slot, half = 0, row;
    if (is3) {
        slot = b >> 1;
        half = b & 1;
        row  = slot * 64;
    } else {
        slot = 64 + (b - 128);
        row  = c_r4[b - 128];
    }

    // --- Phase 1: dot(inp[row], W1) over 6400 floats (1600 float4) ---
    const float4* x = reinterpret_cast<const float4*>(inp + (size_t)row * 6400);
    const float4* w = reinterpret_cast<const float4*>(W1);

    float sum = 0.f;
    // Front-batch the loads for MLP: thread tid covers {tid, tid+512, tid+1024}
    // plus a tail for tid < 64.
    {
        float4 a0 = x[tid];
        float4 w0 = w[tid];
        float4 a1 = x[tid + 512];
        float4 w1 = w[tid + 512];
        float4 a2 = x[tid + 1024];
        float4 w2 = w[tid + 1024];
        sum = fmaf(a0.x, w0.x, sum); sum = fmaf(a0.y, w0.y, sum);
        sum = fmaf(a0.z, w0.z, sum); sum = fmaf(a0.w, w0.w, sum);
        sum = fmaf(a1.x, w1.x, sum); sum = fmaf(a1.y, w1.y, sum);
        sum = fmaf(a1.z, w1.z, sum); sum = fmaf(a1.w, w1.w, sum);
        sum = fmaf(a2.x, w2.x, sum); sum = fmaf(a2.y, w2.y, sum);
        sum = fmaf(a2.z, w2.z, sum); sum = fmaf(a2.w, w2.w, sum);
        if (tid < 64) {
            float4 a3 = x[tid + 1536];
            float4 w3 = w[tid + 1536];
            sum = fmaf(a3.x, w3.x, sum); sum = fmaf(a3.y, w3.y, sum);
            sum = fmaf(a3.z, w3.z, sum); sum = fmaf(a3.w, w3.w, sum);
        }
    }
    #pragma unroll
    for (int off = 16; off > 0; off >>= 1)
        sum += __shfl_down_sync(0xffffffffu, sum, off);
    if (lane == 0) warp_sums[wid] = sum;
    __syncthreads();
    if (wid == 0) {
        sum = (lane < 16) ? warp_sums[lane] : 0.f;
        #pragma unroll
        for (int off = 8; off > 0; off >>= 1)
            sum += __shfl_down_sync(0xffffffffu, sum, off);
        if (lane == 0) {
            float s = fmaxf(sum + __ldg(b1), 0.f);
            if (is3) {
                float x1 = fmaxf(fmaf(s, __ldg(W2 + 1), __ldg(b2 + 1)), 0.f);
                sh_a = fmaxf(fmaf(x1, __ldg(W3a), __ldg(b3a)), 0.f);
            } else {
                int c = c_c4[slot - 64];
                float x1 = fmaxf(fmaf(s, __ldg(W2 + c), __ldg(b2 + c)), 0.f);
                sh_a = fmaxf(fmaf(x1, __ldg(W4a), __ldg(b4a)), 0.f);
            }
        }
    }
    __syncthreads();
    float a = sh_a;

    // --- Phase 2: stream this block's output slice ---
    if (is3) {
        // Compute the 80 final values once, then replicate to this half's 40 tiles.
        if (tid < 80)
            sh_v[tid] = fmaxf(fmaf(a, __ldg(W3b + tid), __ldg(b3b + tid)), 0.f);
        __syncthreads();

        float* base = out + slot * 80;
        int p_base = half * 40;
        // 40 tiles x 20 float4 = 800 float4 stores over 512 threads
        #pragma unroll
        for (int m = tid; m < 800; m += 512) {
            int p  = p_base + m / 20;
            int k4 = (m % 20) * 4;
            float4 v = *reinterpret_cast<const float4*>(sh_v + k4);
            *reinterpret_cast<float4*>(base + p * 5120 + k4) = v;
        }
    } else {
        int j = slot - 64;
        float* base = out + BIAS_END + j * 513;
        for (int k = tid; k < 513; k += 512)
            base[k] = fmaxf(fmaf(a, __ldg(W4b + k), __ldg(b4b + k)), 0.f);
        if (j == 0 && tid < 64)
            out[SEG3_END + tid] = 0.f;
    }
}

extern "C" void kernel_launch(void* const* d_in, const int* in_sizes, int n_in,
                              void* d_out, int out_size) {
    const float* inputs = (const float*)d_in[0];
    const float* W1  = (const float*)d_in[1];
    const float* b1  = (const float*)d_in[2];
    const float* W2  = (const float*)d_in[3];
    const float* b2  = (const float*)d_in[4];
    const float* W3a = (const float*)d_in[5];
    const float* b3a = (const float*)d_in[6];
    const float* W3b = (const float*)d_in[7];
    const float* b3b = (const float*)d_in[8];
    const float* W4a = (const float*)d_in[9];
    const float* b4a = (const float*)d_in[10];
    const float* W4b = (const float*)d_in[11];
    const float* b4b = (const float*)d_in[12];
    float* out = (float*)d_out;

    fused_kernel<<<134, 512>>>(inputs, W1, b1, W2, b2, W3a, b3a, W3b, b3b,
                               W4a, b4a, W4b, b4b, out);
}